// round 13
// baseline (speedup 1.0000x reference)
#include <cuda_runtime.h>
#include <cuda_fp16.h>
#include <math.h>
#include <stdint.h>

// Problem dims (fixed)
#define BB   256      // batch
#define LL   64       // seq len
#define DD   256      // input dim
#define HH   512      // hidden
#define G4   2048     // 4*H

#define NBLK 128      // persistent grid: 8 batch groups x 16 unit slices
#define NGRP 8        // barrier domains (16 blocks each)
#define MB   32       // batch rows per block
#define UB   32       // units per block (x4 gates = 128 gate-cols)

// -------- scratch (device globals: allocation-free) --------
__device__ float  g_a[BB * DD];                   // attention weights a[b,d]
__device__ float  g_Gx[(size_t)BB * LL * G4];     // 128 MB
__device__ __half g_h[2 * BB * HH];               // ping-pong h (fp16)
__device__ unsigned g_ctr[NGRP][LL];              // per-group per-step arrival counters

// ---------- helpers ----------
__device__ __forceinline__ void mma16(float* c,
                                      uint32_t a0, uint32_t a1, uint32_t a2, uint32_t a3,
                                      uint32_t b0, uint32_t b1)
{
    asm volatile("mma.sync.aligned.m16n8k16.row.col.f32.f16.f16.f32 "
                 "{%0,%1,%2,%3},{%4,%5,%6,%7},{%8,%9},{%0,%1,%2,%3};"
                 : "+f"(c[0]), "+f"(c[1]), "+f"(c[2]), "+f"(c[3])
                 : "r"(a0), "r"(a1), "r"(a2), "r"(a3), "r"(b0), "r"(b1));
}

__device__ __forceinline__ void cpa16(void* dst, const void* src) {
    uint32_t d = (uint32_t)__cvta_generic_to_shared(dst);
    asm volatile("cp.async.cg.shared.global [%0], [%1], 16;" :: "r"(d), "l"(src));
}
#define CPA_COMMIT() asm volatile("cp.async.commit_group;")
#define CPA_WAIT0()  asm volatile("cp.async.wait_group 0;")

__device__ __forceinline__ void bar_arrive(unsigned* p) {
    asm volatile("red.release.gpu.global.add.u32 [%0], 1;" :: "l"(p) : "memory");
}
__device__ __forceinline__ unsigned ld_acq(const unsigned* p) {
    unsigned v;
    asm volatile("ld.acquire.gpu.global.u32 %0, [%1];" : "=r"(v) : "l"(p) : "memory");
    return v;
}

__device__ __forceinline__ float sigf(float x) {
    return __fdividef(1.f, 1.f + __expf(-x));
}
__device__ __forceinline__ float tanhfast(float x) {
    return __fmaf_rn(2.f, __fdividef(1.f, 1.f + __expf(-2.f * x)), -1.f);
}

// ============================================================
// Kernel 1a: a = softmax_d(x^T @ Wx) -> g_a   (softmax only)
// (recurrent logit term is constant over softmax axis -> cancels)
// ============================================================
__global__ void attn_kernel(const float* __restrict__ x,
                            const float* __restrict__ Wa)
{
    __shared__ float wx[LL];
    __shared__ float red[DD];
    const int b = blockIdx.x;
    const int d = threadIdx.x;

    if (d < LL) wx[d] = Wa[2 * HH + d];
    __syncthreads();

    const float* xb = x + (size_t)b * LL * DD;
    float ex = 0.f;
#pragma unroll
    for (int l = 0; l < LL; ++l)
        ex += xb[l * DD + d] * wx[l];

    red[d] = ex; __syncthreads();
    for (int s = DD / 2; s > 0; s >>= 1) {
        if (d < s) red[d] = fmaxf(red[d], red[d + s]);
        __syncthreads();
    }
    const float mx = red[0];
    __syncthreads();

    const float e = expf(ex - mx);
    red[d] = e; __syncthreads();
    for (int s = DD / 2; s > 0; s >>= 1) {
        if (d < s) red[d] += red[d + s];
        __syncthreads();
    }
    g_a[b * DD + d] = e / red[0];
}

// ============================================================
// Kernel 1b: att[b,t,:] = a[b,:] — full-chip streaming broadcast write
// ============================================================
__global__ void att_write(float* __restrict__ att)
{
    const int idx = blockIdx.x * blockDim.x + threadIdx.x;  // one float4
    const int d4 = idx & 63;              // DD/4
    const int t  = (idx >> 6) & 63;
    const int b  = idx >> 12;
    const float4 v = *(const float4*)&g_a[b * DD + d4 * 4];
    *(float4*)&att[((size_t)b * LL + t) * DD + d4 * 4] = v;
}

// ============================================================
// Kernel 2: Gx = (a .* x) @ Wih^T + b_ih + b_hh  (16384x2048x256)
// fp16 operands (same 10-bit mantissa as tf32), f32 accumulate,
// m16n8k16 -> HALF the HMMA instruction count of the tf32 version.
// Whole K=256 resident in smem; one sync; BM=128 BN=64.
// ============================================================
#define XA_H (4 * 128 * 72)               // A: 4 chunks x 128 rows x 72 halves
#define XB_H (4 * 64 * 72)                // B: 4 chunks x 64 rows x 72 halves
#define SMEM_XP ((XA_H + XB_H) * 2)       // 110592 B

__global__ __launch_bounds__(256) void gemm_xproj_f16(
    const float* __restrict__ X,
    const float* __restrict__ Bw,
    const float* __restrict__ b1,
    const float* __restrict__ b2,
    float* __restrict__ C)
{
    extern __shared__ __align__(16) __half smx[];
    __half* As = smx;                     // [4][128][72]
    __half* Bs = smx + XA_H;              // [4][64][72]

    const int tid  = threadIdx.x;
    const int lane = tid & 31, warp = tid >> 5;
    const int qid  = lane >> 2, tig = lane & 3;
    const int wm   = warp >> 1;           // 0..3 : 32-row group
    const int wn   = warp & 1;            // 0..1 : 32-col group
    const int m0   = blockIdx.y * 128;
    const int n0   = blockIdx.x * 64;

    // ---- A tile: (a .* x) -> fp16, chunked layout ----
    {
        const int r   = tid >> 1;         // 0..127
        const int ch0 = (tid & 1) * 2;    // chunks {0,1} or {2,3}
        const int b   = (m0 + r) >> 6;    // batch of row
#pragma unroll
        for (int cc = 0; cc < 2; ++cc) {
            const int ch = ch0 + cc;
            const float* xp = X   + (size_t)(m0 + r) * DD + ch * 64;
            const float* ap = g_a + b * DD + ch * 64;
            __half* dst = As + (ch * 128 + r) * 72;
#pragma unroll
            for (int q = 0; q < 16; ++q) {
                const float4 xv = *(const float4*)(xp + q * 4);
                const float4 av = *(const float4*)(ap + q * 4);
                __half2 h2[2];
                h2[0] = __floats2half2_rn(xv.x * av.x, xv.y * av.y);
                h2[1] = __floats2half2_rn(xv.z * av.z, xv.w * av.w);
                *(uint2*)(dst + q * 4) = *(const uint2*)h2;
            }
        }
    }
    // ---- B tile: Wih -> fp16, chunked layout ----
    {
        const int n  = tid >> 2;          // 0..63
        const int ch = tid & 3;
        const float* wp = Bw + (size_t)(n0 + n) * DD + ch * 64;
        __half* dst = Bs + (ch * 64 + n) * 72;
#pragma unroll
        for (int q = 0; q < 16; ++q) {
            const float4 wv = *(const float4*)(wp + q * 4);
            __half2 h2[2];
            h2[0] = __floats2half2_rn(wv.x, wv.y);
            h2[1] = __floats2half2_rn(wv.z, wv.w);
            *(uint2*)(dst + q * 4) = *(const uint2*)h2;
        }
    }
    __syncthreads();

    float acc[2][4][4] = {};
#pragma unroll
    for (int ch = 0; ch < 4; ++ch) {
        const __half* hA = As + ch * 128 * 72;
        const __half* wB = Bs + ch * 64 * 72;
#pragma unroll
        for (int kk = 0; kk < 4; ++kk) {
            uint32_t af[2][4], bf[4][2];
#pragma unroll
            for (int mt = 0; mt < 2; ++mt) {
                const __half* s = hA + (wm * 32 + mt * 16 + qid) * 72 + kk * 16 + tig * 2;
                af[mt][0] = *(const uint32_t*)(s);
                af[mt][1] = *(const uint32_t*)(s + 8 * 72);
                af[mt][2] = *(const uint32_t*)(s + 8);
                af[mt][3] = *(const uint32_t*)(s + 8 * 72 + 8);
            }
#pragma unroll
            for (int nt = 0; nt < 4; ++nt) {
                const __half* s = wB + (wn * 32 + nt * 8 + qid) * 72 + kk * 16 + tig * 2;
                bf[nt][0] = *(const uint32_t*)(s);
                bf[nt][1] = *(const uint32_t*)(s + 8);
            }
#pragma unroll
            for (int mt = 0; mt < 2; ++mt)
#pragma unroll
                for (int nt = 0; nt < 4; ++nt)
                    mma16(acc[mt][nt], af[mt][0], af[mt][1], af[mt][2], af[mt][3],
                          bf[nt][0], bf[nt][1]);
        }
    }

#pragma unroll
    for (int mt = 0; mt < 2; ++mt) {
        const int m = m0 + wm * 32 + mt * 16 + qid;
#pragma unroll
        for (int nt = 0; nt < 4; ++nt) {
            const int n = n0 + wn * 32 + nt * 8 + 2 * tig;
            const float bb0 = b1[n] + b2[n];
            const float bb1 = b1[n + 1] + b2[n + 1];
            float2 o0 = {acc[mt][nt][0] + bb0, acc[mt][nt][1] + bb1};
            float2 o1 = {acc[mt][nt][2] + bb0, acc[mt][nt][3] + bb1};
            *(float2*)(C + (size_t)m * G4 + n)       = o0;
            *(float2*)(C + (size_t)(m + 8) * G4 + n) = o1;
        }
    }
}

// ============================================================
// Kernel 3: PERSISTENT fp16 recurrence.
// 128 blocks = 8 batch groups x 16 unit slices; block tile
// 32 batch x 128 gate-cols, K=512. Whh resident in smem (fp16).
// Gx register LDGs issued AFTER the h cp.async group so the
// L2-resident h tile is never queued behind DRAM loads.
// ============================================================
#define WHH_H  (128 * 520)                // Whh slice, fp16 halves
#define HCH_H  (32 * 72)                  // one 64-K h chunk, fp16 halves
#define GT_F   (2 * 32 * 132)             // 2-plane partial-sum exchange, f32
#define SMEM_REC (WHH_H * 2 + 8 * HCH_H * 2 + GT_F * 4)   // 203776 B

__global__ void __launch_bounds__(256, 1) rec_persistent(
    const float* __restrict__ h0,
    const float* __restrict__ c0,
    const float* __restrict__ Whh,
    const float* __restrict__ Gx,
    float* __restrict__ enc,
    __half* __restrict__ hbuf)
{
    extern __shared__ __align__(16) __half smh[];
    __half* WhhS = smh;                         // [128][520]
    __half* hS   = smh + WHH_H;                 // [8][32][72]
    float*  Gt   = (float*)(smh + WHH_H + 8 * HCH_H);  // [2][32][132]

    const int tid  = threadIdx.x;
    const int lane = tid & 31, warp = tid >> 5;
    const int qid  = lane >> 2, tig = lane & 3;
    const int set  = warp >> 2;                 // K half: 0 -> chunks 0-3, 1 -> 4-7
    const int gate = warp & 3;                  // 32-col group
    const int bid  = blockIdx.x;
    const int grp  = bid >> 4;                  // batch group 0..7
    const int m0   = grp * MB;
    const int u0   = (bid & 15) * UB;

    // ---- Whh slice -> smem fp16 (once) ----
    for (int idx = tid; idx < 128 * 128; idx += 256) {
        const int r = idx >> 7, kq = (idx & 127) * 4;
        const float4 v = *(const float4*)&Whh[(size_t)((r >> 5) * HH + u0 + (r & 31)) * HH + kq];
        *(__half2*)&WhhS[r * 520 + kq]     = __floats2half2_rn(v.x, v.y);
        *(__half2*)&WhhS[r * 520 + kq + 2] = __floats2half2_rn(v.z, v.w);
    }

    // ---- h(0) slice -> fp16 ping buffer 0 ----
    for (int idx = tid; idx < MB * UB; idx += 256) {
        const int b = idx >> 5, uu = idx & 31;
        hbuf[(size_t)(m0 + b) * HH + u0 + uu] =
            __float2half_rn(h0[(size_t)(m0 + b) * HH + u0 + uu]);
    }

    // ---- c slice in registers ----
    const int cb = tid >> 3;                    // 0..31 (batch rel)
    const int cu = (tid & 7) * 4;               // unit rel, step 4
    float creg[4];
    {
        const float4 cv = *(const float4*)&c0[(size_t)(m0 + cb) * HH + u0 + cu];
        creg[0] = cv.x; creg[1] = cv.y; creg[2] = cv.z; creg[3] = cv.w;
    }

    __syncthreads();                            // h(0)+Whh writes done block-wide
    if (tid == 0) bar_arrive(&g_ctr[grp][0]);   // publish h(0)

    // per-set h-load indices: 128 threads cover 4 chunks x 4KB
    const int stid = tid & 127;
    const int hr = stid >> 2;                   // row 0..31
    const int hq = (stid & 3) * 8;              // halves 0,8,16,24 (+32 second load)

    // Gx base for this thread's cell tile (advance by G4 per step)
    const float* gxp = Gx + ((size_t)(m0 + cb) * LL) * G4 + u0 + cu;

    for (int t = 0; t < LL; ++t) {
        const __half* hsrc = hbuf + (size_t)(t & 1) * BB * HH;
        __half*       hdst = hbuf + (size_t)((t + 1) & 1) * BB * HH;

        // ---- per-WARP barrier poll: h(t) ready from the 16 peer blocks ----
        if (lane == 0) {
            const unsigned* ctr = &g_ctr[grp][t];
            while (ld_acq(ctr) < 16u) {}
        }
        __syncwarp();

        // ---- this set loads ITS 4 chunks (16 KB) FIRST ----
#pragma unroll
        for (int j = 0; j < 4; ++j) {
            const int p = set * 4 + j;
            const __half* src = hsrc + (size_t)(m0 + hr) * HH + p * 64;
            cpa16(&hS[p * HCH_H + hr * 72 + hq],      src + hq);
            cpa16(&hS[p * HCH_H + hr * 72 + hq + 32], src + hq + 32);
        }
        CPA_COMMIT();

        // ---- Gx -> registers (behind the h tile in the queue;
        //      latency hidden by the MMA loop, consumed at the cell) ----
        float gx[4][4];
        {
            const float* gb = gxp + (size_t)t * G4;
#pragma unroll
            for (int g = 0; g < 4; ++g) {
                const float4 v = *(const float4*)(gb + g * HH);
                gx[g][0] = v.x; gx[g][1] = v.y; gx[g][2] = v.z; gx[g][3] = v.w;
            }
        }

        CPA_WAIT0();                            // h tile only (L2-resident)
        asm volatile("bar.sync %0, %1;" :: "r"(1 + set), "r"(128) : "memory");

        // ---- sync-free MMA loop on this set's contiguous K half ----
        float acc[2][4][4] = {};
#pragma unroll
        for (int j = 0; j < 4; ++j) {
            const int kc = set * 4 + j;
            const __half* hA = hS + kc * HCH_H;
            const __half* wB = WhhS + kc * 64;
#pragma unroll
            for (int kk = 0; kk < 4; ++kk) {
                uint32_t af[2][4], bf[4][2];
#pragma unroll
                for (int mt = 0; mt < 2; ++mt) {
                    const __half* s = hA + (mt * 16 + qid) * 72 + kk * 16 + tig * 2;
                    af[mt][0] = *(const uint32_t*)(s);
                    af[mt][1] = *(const uint32_t*)(s + 8 * 72);
                    af[mt][2] = *(const uint32_t*)(s + 8);
                    af[mt][3] = *(const uint32_t*)(s + 8 * 72 + 8);
                }
#pragma unroll
                for (int nt = 0; nt < 4; ++nt) {
                    const __half* s = wB + (gate * 32 + nt * 8 + qid) * 520 + kk * 16 + tig * 2;
                    bf[nt][0] = *(const uint32_t*)(s);
                    bf[nt][1] = *(const uint32_t*)(s + 8);
                }
#pragma unroll
                for (int mt = 0; mt < 2; ++mt)
#pragma unroll
                    for (int nt = 0; nt < 4; ++nt)
                        mma16(acc[mt][nt], af[mt][0], af[mt][1], af[mt][2], af[mt][3],
                              bf[nt][0], bf[nt][1]);
            }
        }

        // ---- epilogue: partials -> 2-plane Gt (disjoint per set) ----
        {
            float* Gp = Gt + set * (32 * 132);
#pragma unroll
            for (int mt = 0; mt < 2; ++mt) {
                const int rl = mt * 16 + qid;
#pragma unroll
                for (int nt = 0; nt < 4; ++nt) {
                    const int cl = gate * 32 + nt * 8 + tig * 2;
                    *(float2*)&Gp[rl * 132 + cl]       = make_float2(acc[mt][nt][0], acc[mt][nt][1]);
                    *(float2*)&Gp[(rl + 8) * 132 + cl] = make_float2(acc[mt][nt][2], acc[mt][nt][3]);
                }
            }
        }
        __syncthreads();                        // block sync #1: Gt complete

        // ---- LSTM cell: sum partials + register Gx; fast transcendentals ----
        {
            float gv[4][4];
#pragma unroll
            for (int g = 0; g < 4; ++g) {
                const int off = cb * 132 + g * 32 + cu;
                const float4 p0 = *(const float4*)&Gt[off];
                const float4 p1 = *(const float4*)&Gt[32 * 132 + off];
                gv[g][0] = p0.x + p1.x + gx[g][0];
                gv[g][1] = p0.y + p1.y + gx[g][1];
                gv[g][2] = p0.z + p1.z + gx[g][2];
                gv[g][3] = p0.w + p1.w + gx[g][3];
            }

            float4 ho;
            float* hop = &ho.x;
            __half hr4[4];
#pragma unroll
            for (int k = 0; k < 4; ++k) {
                const float si = sigf(gv[0][k]);
                const float sf = sigf(gv[1][k]);
                const float so = sigf(gv[3][k]);
                const float cn = sf * creg[k] + si * tanhfast(gv[2][k]);
                const float hn = so * tanhfast(cn);
                creg[k] = cn;
                hop[k] = hn;
                hr4[k] = __float2half_rn(hn);
            }
            *(float4*)(enc + (size_t)(m0 + cb) * LL * HH + (size_t)t * HH + u0 + cu) = ho;
            *(uint2*)(hdst + (size_t)(m0 + cb) * HH + u0 + cu) = *(const uint2*)hr4;
        }
        __syncthreads();                        // block sync #2: hdst/Gt done
        if (tid == 0 && t + 1 < LL) bar_arrive(&g_ctr[grp][t + 1]);
    }
}

// ============================================================
// Launch
// ============================================================
extern "C" void kernel_launch(void* const* d_in, const int* in_sizes, int n_in,
                              void* d_out, int out_size)
{
    (void)in_sizes; (void)n_in; (void)out_size;
    const float* x   = (const float*)d_in[0];
    const float* h0  = (const float*)d_in[1];
    const float* c0  = (const float*)d_in[2];
    const float* Wih = (const float*)d_in[3];
    const float* Whh = (const float*)d_in[4];
    const float* bih = (const float*)d_in[5];
    const float* bhh = (const float*)d_in[6];
    const float* Wa  = (const float*)d_in[7];
    // d_in[8] = ba: cancels inside softmax, never read.

    float* att = (float*)d_out;                       // (B, L, D)
    float* enc = att + (size_t)BB * LL * DD;          // (B, L, H)

    float *gx;
    __half* hbuf;
    void* ctr;
    cudaGetSymbolAddress((void**)&gx,   g_Gx);
    cudaGetSymbolAddress((void**)&hbuf, g_h);
    cudaGetSymbolAddress(&ctr,          g_ctr);

    static int smem_set = 0;
    if (!smem_set) {
        cudaFuncSetAttribute(rec_persistent,
                             cudaFuncAttributeMaxDynamicSharedMemorySize, SMEM_REC);
        cudaFuncSetAttribute(gemm_xproj_f16,
                             cudaFuncAttributeMaxDynamicSharedMemorySize, SMEM_XP);
        smem_set = 1;
    }

    // 0) zero per-step barrier counters (captured memset node)
    cudaMemsetAsync(ctr, 0, sizeof(unsigned) * NGRP * LL);

    // 1) attention softmax (g_a) + full-chip broadcast write of att
    attn_kernel<<<BB, DD>>>(x, Wa);
    att_write<<<(BB * LL * DD / 4) / 256, 256>>>(att);

    // 2) input projection, fp16 tensor cores (a-scaling fused)
    {
        dim3 grid(G4 / 64, (BB * LL) / 128);
        gemm_xproj_f16<<<grid, 256, SMEM_XP>>>(x, Wih, bih, bhh, gx);
    }

    // 3) whole recurrence in ONE persistent fp16 kernel
    rec_persistent<<<NBLK, 256, SMEM_REC>>>(h0, c0, Whh, gx, enc, hbuf);
}

// round 15
// speedup vs baseline: 1.5795x; 1.5795x over previous
#include <cuda_runtime.h>
#include <cuda_fp16.h>
#include <math.h>
#include <stdint.h>

// Problem dims (fixed)
#define BB   256      // batch
#define LL   64       // seq len
#define DD   256      // input dim
#define HH   512      // hidden
#define G4   2048     // 4*H

#define NBLK 128      // persistent grid: 8 batch groups x 16 unit slices
#define NGRP 8        // barrier domains (16 blocks each)
#define MB   32       // batch rows per block
#define UB   32       // units per block (x4 gates = 128 gate-cols)

// -------- scratch (device globals: allocation-free) --------
__device__ float  g_a[BB * DD];                   // attention weights a[b,d]
__device__ float  g_Gx[(size_t)BB * LL * G4];     // 128 MB
__device__ __half g_h[2 * BB * HH];               // ping-pong h (fp16)
__device__ unsigned g_ctr[NGRP][LL];              // per-group per-step arrival counters

// ---------- helpers ----------
__device__ __forceinline__ void mma16(float* c,
                                      uint32_t a0, uint32_t a1, uint32_t a2, uint32_t a3,
                                      uint32_t b0, uint32_t b1)
{
    asm volatile("mma.sync.aligned.m16n8k16.row.col.f32.f16.f16.f32 "
                 "{%0,%1,%2,%3},{%4,%5,%6,%7},{%8,%9},{%0,%1,%2,%3};"
                 : "+f"(c[0]), "+f"(c[1]), "+f"(c[2]), "+f"(c[3])
                 : "r"(a0), "r"(a1), "r"(a2), "r"(a3), "r"(b0), "r"(b1));
}

__device__ __forceinline__ void cpa16(void* dst, const void* src) {
    uint32_t d = (uint32_t)__cvta_generic_to_shared(dst);
    asm volatile("cp.async.cg.shared.global [%0], [%1], 16;" :: "r"(d), "l"(src));
}
#define CPA_COMMIT() asm volatile("cp.async.commit_group;")
#define CPA_WAIT0()  asm volatile("cp.async.wait_group 0;")

__device__ __forceinline__ void bar_arrive(unsigned* p) {
    asm volatile("red.release.gpu.global.add.u32 [%0], 1;" :: "l"(p) : "memory");
}
__device__ __forceinline__ unsigned ld_acq(const unsigned* p) {
    unsigned v;
    asm volatile("ld.acquire.gpu.global.u32 %0, [%1];" : "=r"(v) : "l"(p) : "memory");
    return v;
}

__device__ __forceinline__ float sigf(float x) {
    return __fdividef(1.f, 1.f + __expf(-x));
}
__device__ __forceinline__ float tanhfast(float x) {
    return __fmaf_rn(2.f, __fdividef(1.f, 1.f + __expf(-2.f * x)), -1.f);
}

// ============================================================
// Kernel 1: a = softmax_d(x^T @ Wx); att = a (all t); store a[b,d]
// (recurrent logit term is constant over softmax axis -> cancels)
// ============================================================
__global__ void attn_kernel(const float* __restrict__ x,
                            const float* __restrict__ Wa,
                            float* __restrict__ att)
{
    __shared__ float wx[LL];
    __shared__ float red[DD];
    const int b = blockIdx.x;
    const int d = threadIdx.x;

    if (d < LL) wx[d] = Wa[2 * HH + d];
    __syncthreads();

    const float* xb = x + (size_t)b * LL * DD;
    float ex = 0.f;
#pragma unroll
    for (int l = 0; l < LL; ++l)
        ex += xb[l * DD + d] * wx[l];

    red[d] = ex; __syncthreads();
    for (int s = DD / 2; s > 0; s >>= 1) {
        if (d < s) red[d] = fmaxf(red[d], red[d + s]);
        __syncthreads();
    }
    const float mx = red[0];
    __syncthreads();

    const float e = expf(ex - mx);
    red[d] = e; __syncthreads();
    for (int s = DD / 2; s > 0; s >>= 1) {
        if (d < s) red[d] += red[d + s];
        __syncthreads();
    }
    const float a = e / red[0];

    g_a[b * DD + d] = a;

    __syncthreads();                 // red[0] consumed by all before reuse
    red[d] = a;                      // broadcast a for vectorized stores
    __syncthreads();

    float* attb = att + (size_t)b * LL * DD;
    const int d4 = (d & 63) * 4;
    const float4 av = *(const float4*)&red[d4];
#pragma unroll
    for (int tt = d >> 6; tt < LL; tt += 4)
        *(float4*)&attb[tt * DD + d4] = av;
}

// ============================================================
// Kernel 2: Gx = (a .* x) @ Wih^T + b_ih + b_hh  (16384x2048x256)
// fp16 m16n8k16 (HALF the instructions of tf32 k8; same 10-bit
// mantissa), f32 accumulate. BM=128 BN=128 BK=32, register-
// prefetch pipeline (validated tf32 skeleton). Warps: 2(m) x 4(n),
// warp tile 64x32.
// ============================================================
__global__ __launch_bounds__(256) void gemm_xproj_f16(
    const float* __restrict__ X,
    const float* __restrict__ Bw,
    const float* __restrict__ b1,
    const float* __restrict__ b2,
    float* __restrict__ C)
{
    __shared__ __half As[128 * 40];   // [row][k] halves, stride 40 (conflict-free)
    __shared__ __half Bs[128 * 40];

    const int tid  = threadIdx.x;
    const int lane = tid & 31, warp = tid >> 5;
    const int qid  = lane >> 2, tig = lane & 3;
    const int wm   = warp >> 2;       // 0..1 : 64-row group
    const int wn   = warp & 3;        // 0..3 : 32-col group
    const int m0   = blockIdx.y * 128;
    const int n0   = blockIdx.x * 128;

    const int lr = tid >> 3;          // 0..31
    const int lk = (tid & 7) * 4;     // 0..28

    const float* aptr = X  + (size_t)(m0 + lr) * DD + lk;
    const float* bptr = Bw + (size_t)(n0 + lr) * DD + lk;
    int brow[4];
#pragma unroll
    for (int i = 0; i < 4; ++i) brow[i] = (m0 + lr + i * 32) >> 6;

    float4 pa[4], sa[4], pb[4];
#pragma unroll
    for (int i = 0; i < 4; ++i) {
        pa[i] = *(const float4*)(aptr + (size_t)i * 32 * DD);
        sa[i] = *(const float4*)(g_a + brow[i] * DD + lk);
        pb[i] = *(const float4*)(bptr + (size_t)i * 32 * DD);
    }

    float acc[4][4][4] = {};

    for (int k0 = 0; k0 < DD; k0 += 32) {
#pragma unroll
        for (int i = 0; i < 4; ++i) {
            __half* d = &As[(lr + i * 32) * 40 + lk];
            __half2 h0 = __floats2half2_rn(pa[i].x * sa[i].x, pa[i].y * sa[i].y);
            __half2 h1 = __floats2half2_rn(pa[i].z * sa[i].z, pa[i].w * sa[i].w);
            *(__half2*)(d)     = h0;
            *(__half2*)(d + 2) = h1;
            __half* e = &Bs[(lr + i * 32) * 40 + lk];
            __half2 g0 = __floats2half2_rn(pb[i].x, pb[i].y);
            __half2 g1 = __floats2half2_rn(pb[i].z, pb[i].w);
            *(__half2*)(e)     = g0;
            *(__half2*)(e + 2) = g1;
        }
        __syncthreads();

        if (k0 + 32 < DD) {
#pragma unroll
            for (int i = 0; i < 4; ++i) {
                pa[i] = *(const float4*)(aptr + k0 + 32 + (size_t)i * 32 * DD);
                sa[i] = *(const float4*)(g_a + brow[i] * DD + k0 + 32 + lk);
                pb[i] = *(const float4*)(bptr + k0 + 32 + (size_t)i * 32 * DD);
            }
        }

#pragma unroll
        for (int kk = 0; kk < 2; ++kk) {        // two k16 steps per 32-chunk
            uint32_t af[4][4], bf[4][2];
#pragma unroll
            for (int mt = 0; mt < 4; ++mt) {
                const __half* s = &As[(wm * 64 + mt * 16 + qid) * 40 + kk * 16 + tig * 2];
                af[mt][0] = *(const uint32_t*)(s);
                af[mt][1] = *(const uint32_t*)(s + 8 * 40);
                af[mt][2] = *(const uint32_t*)(s + 8);
                af[mt][3] = *(const uint32_t*)(s + 8 * 40 + 8);
            }
#pragma unroll
            for (int nt = 0; nt < 4; ++nt) {
                const __half* s = &Bs[(wn * 32 + nt * 8 + qid) * 40 + kk * 16 + tig * 2];
                bf[nt][0] = *(const uint32_t*)(s);
                bf[nt][1] = *(const uint32_t*)(s + 8);
            }
#pragma unroll
            for (int mt = 0; mt < 4; ++mt)
#pragma unroll
                for (int nt = 0; nt < 4; ++nt)
                    mma16(acc[mt][nt], af[mt][0], af[mt][1], af[mt][2], af[mt][3],
                          bf[nt][0], bf[nt][1]);
        }
        __syncthreads();
    }

#pragma unroll
    for (int mt = 0; mt < 4; ++mt) {
        const int m = m0 + wm * 64 + mt * 16 + qid;
#pragma unroll
        for (int nt = 0; nt < 4; ++nt) {
            const int n = n0 + wn * 32 + nt * 8 + 2 * tig;
            const float bb0 = b1[n] + b2[n];
            const float bb1 = b1[n + 1] + b2[n + 1];
            float2 o0 = {acc[mt][nt][0] + bb0, acc[mt][nt][1] + bb1};
            float2 o1 = {acc[mt][nt][2] + bb0, acc[mt][nt][3] + bb1};
            *(float2*)(C + (size_t)m * G4 + n)       = o0;
            *(float2*)(C + (size_t)(m + 8) * G4 + n) = o1;
        }
    }
}

// ============================================================
// Kernel 3: PERSISTENT fp16 recurrence (round-11 version — best).
// 128 blocks = 8 batch groups x 16 unit slices; block tile
// 32 batch x 128 gate-cols, K=512. Whh resident in smem (fp16).
// GxS via cp.async smem prefetch pre-barrier; warp-autonomous
// barrier polling; contiguous K-split with per-set named barriers.
// ============================================================
#define WHH_H  (128 * 520)                // Whh slice, fp16 halves
#define HCH_H  (32 * 72)                  // one 64-K h chunk, fp16 halves
#define GX_F   (32 * 132)                 // Gx tile, f32
#define GT_F   (2 * 32 * 132)             // 2-plane partial-sum exchange, f32
#define SMEM_REC (WHH_H * 2 + 8 * HCH_H * 2 + GX_F * 4 + GT_F * 4)  // 220672 B

__global__ void __launch_bounds__(256, 1) rec_persistent(
    const float* __restrict__ h0,
    const float* __restrict__ c0,
    const float* __restrict__ Whh,
    const float* __restrict__ Gx,
    float* __restrict__ enc,
    __half* __restrict__ hbuf)
{
    extern __shared__ __align__(16) __half smh[];
    __half* WhhS = smh;                         // [128][520]
    __half* hS   = smh + WHH_H;                 // [8][32][72]
    float*  GxS  = (float*)(smh + WHH_H + 8 * HCH_H);  // [32][132]
    float*  Gt   = GxS + GX_F;                  // [2][32][132]

    const int tid  = threadIdx.x;
    const int lane = tid & 31, warp = tid >> 5;
    const int qid  = lane >> 2, tig = lane & 3;
    const int set  = warp >> 2;                 // K half: 0 -> chunks 0-3, 1 -> 4-7
    const int gate = warp & 3;                  // 32-col group
    const int bid  = blockIdx.x;
    const int grp  = bid >> 4;                  // batch group 0..7
    const int m0   = grp * MB;
    const int u0   = (bid & 15) * UB;

    // ---- Whh slice -> smem fp16 (once) ----
    for (int idx = tid; idx < 128 * 128; idx += 256) {
        const int r = idx >> 7, kq = (idx & 127) * 4;
        const float4 v = *(const float4*)&Whh[(size_t)((r >> 5) * HH + u0 + (r & 31)) * HH + kq];
        *(__half2*)&WhhS[r * 520 + kq]     = __floats2half2_rn(v.x, v.y);
        *(__half2*)&WhhS[r * 520 + kq + 2] = __floats2half2_rn(v.z, v.w);
    }

    // ---- h(0) slice -> fp16 ping buffer 0 ----
    for (int idx = tid; idx < MB * UB; idx += 256) {
        const int b = idx >> 5, uu = idx & 31;
        hbuf[(size_t)(m0 + b) * HH + u0 + uu] =
            __float2half_rn(h0[(size_t)(m0 + b) * HH + u0 + uu]);
    }

    // ---- c slice in registers ----
    const int cb = tid >> 3;                    // 0..31 (batch rel)
    const int cu = (tid & 7) * 4;               // unit rel, step 4
    float creg[4];
    {
        const float4 cv = *(const float4*)&c0[(size_t)(m0 + cb) * HH + u0 + cu];
        creg[0] = cv.x; creg[1] = cv.y; creg[2] = cv.z; creg[3] = cv.w;
    }

    __syncthreads();                            // h(0)+Whh writes done block-wide
    if (tid == 0) bar_arrive(&g_ctr[grp][0]);   // publish h(0)

    // per-set h-load indices: 128 threads cover 4 chunks x 4KB
    const int stid = tid & 127;
    const int hr = stid >> 2;                   // row 0..31
    const int hq = (stid & 3) * 8;              // halves 0,8,16,24 (+32 second load)

    for (int t = 0; t < LL; ++t) {
        const __half* hsrc = hbuf + (size_t)(t & 1) * BB * HH;
        __half*       hdst = hbuf + (size_t)((t + 1) & 1) * BB * HH;

        // Gx prefetch for this step (static input; overlaps barrier wait)
        {
            const float* gbase = Gx + ((size_t)m0 * LL + t) * G4 + u0;
#pragma unroll
            for (int i = 0; i < 4; ++i) {
                const int idx = tid + i * 256;
                const int b = idx >> 5, g = (idx >> 3) & 3, q = (idx & 7) * 4;
                cpa16(&GxS[b * 132 + g * 32 + q],
                      gbase + (size_t)b * LL * G4 + g * HH + q);
            }
            CPA_COMMIT();
        }

        // ---- per-WARP barrier poll: h(t) ready from the 16 peer blocks ----
        if (lane == 0) {
            const unsigned* ctr = &g_ctr[grp][t];
            while (ld_acq(ctr) < 16u) {}
        }
        __syncwarp();

        // ---- this set loads ITS 4 chunks (16 KB), syncs on named barrier ----
#pragma unroll
        for (int j = 0; j < 4; ++j) {
            const int p = set * 4 + j;
            const __half* src = hsrc + (size_t)(m0 + hr) * HH + p * 64;
            cpa16(&hS[p * HCH_H + hr * 72 + hq],      src + hq);
            cpa16(&hS[p * HCH_H + hr * 72 + hq + 32], src + hq + 32);
        }
        CPA_COMMIT();
        CPA_WAIT0();                            // drains Gx group too
        asm volatile("bar.sync %0, %1;" :: "r"(1 + set), "r"(128) : "memory");

        // ---- sync-free MMA loop on this set's contiguous K half ----
        float acc[2][4][4] = {};
#pragma unroll
        for (int j = 0; j < 4; ++j) {
            const int kc = set * 4 + j;
            const __half* hA = hS + kc * HCH_H;
            const __half* wB = WhhS + kc * 64;
#pragma unroll
            for (int kk = 0; kk < 4; ++kk) {
                uint32_t af[2][4], bf[4][2];
#pragma unroll
                for (int mt = 0; mt < 2; ++mt) {
                    const __half* s = hA + (mt * 16 + qid) * 72 + kk * 16 + tig * 2;
                    af[mt][0] = *(const uint32_t*)(s);
                    af[mt][1] = *(const uint32_t*)(s + 8 * 72);
                    af[mt][2] = *(const uint32_t*)(s + 8);
                    af[mt][3] = *(const uint32_t*)(s + 8 * 72 + 8);
                }
#pragma unroll
                for (int nt = 0; nt < 4; ++nt) {
                    const __half* s = wB + (gate * 32 + nt * 8 + qid) * 520 + kk * 16 + tig * 2;
                    bf[nt][0] = *(const uint32_t*)(s);
                    bf[nt][1] = *(const uint32_t*)(s + 8);
                }
#pragma unroll
                for (int mt = 0; mt < 2; ++mt)
#pragma unroll
                    for (int nt = 0; nt < 4; ++nt)
                        mma16(acc[mt][nt], af[mt][0], af[mt][1], af[mt][2], af[mt][3],
                              bf[nt][0], bf[nt][1]);
            }
        }

        // ---- epilogue: partials -> 2-plane Gt (disjoint per set) ----
        {
            float* Gp = Gt + set * (32 * 132);
#pragma unroll
            for (int mt = 0; mt < 2; ++mt) {
                const int rl = mt * 16 + qid;
#pragma unroll
                for (int nt = 0; nt < 4; ++nt) {
                    const int cl = gate * 32 + nt * 8 + tig * 2;
                    *(float2*)&Gp[rl * 132 + cl]       = make_float2(acc[mt][nt][0], acc[mt][nt][1]);
                    *(float2*)&Gp[(rl + 8) * 132 + cl] = make_float2(acc[mt][nt][2], acc[mt][nt][3]);
                }
            }
        }
        __syncthreads();                        // block sync #1: Gt complete

        // ---- LSTM cell: sum partials + Gx; fast transcendentals ----
        {
            float gv[4][4];
#pragma unroll
            for (int g = 0; g < 4; ++g) {
                const int off = cb * 132 + g * 32 + cu;
                const float4 p0 = *(const float4*)&Gt[off];
                const float4 p1 = *(const float4*)&Gt[32 * 132 + off];
                const float4 px = *(const float4*)&GxS[off];
                gv[g][0] = p0.x + p1.x + px.x;
                gv[g][1] = p0.y + p1.y + px.y;
                gv[g][2] = p0.z + p1.z + px.z;
                gv[g][3] = p0.w + p1.w + px.w;
            }

            float4 ho;
            float* hop = &ho.x;
            __half hr4[4];
#pragma unroll
            for (int k = 0; k < 4; ++k) {
                const float si = sigf(gv[0][k]);
                const float sf = sigf(gv[1][k]);
                const float so = sigf(gv[3][k]);
                const float cn = sf * creg[k] + si * tanhfast(gv[2][k]);
                const float hn = so * tanhfast(cn);
                creg[k] = cn;
                hop[k] = hn;
                hr4[k] = __float2half_rn(hn);
            }
            *(float4*)(enc + (size_t)(m0 + cb) * LL * HH + (size_t)t * HH + u0 + cu) = ho;
            *(uint2*)(hdst + (size_t)(m0 + cb) * HH + u0 + cu) = *(const uint2*)hr4;
        }
        __syncthreads();                        // block sync #2: hdst/Gt/GxS done
        if (tid == 0 && t + 1 < LL) bar_arrive(&g_ctr[grp][t + 1]);
    }
}

// ============================================================
// Launch
// ============================================================
extern "C" void kernel_launch(void* const* d_in, const int* in_sizes, int n_in,
                              void* d_out, int out_size)
{
    (void)in_sizes; (void)n_in; (void)out_size;
    const float* x   = (const float*)d_in[0];
    const float* h0  = (const float*)d_in[1];
    const float* c0  = (const float*)d_in[2];
    const float* Wih = (const float*)d_in[3];
    const float* Whh = (const float*)d_in[4];
    const float* bih = (const float*)d_in[5];
    const float* bhh = (const float*)d_in[6];
    const float* Wa  = (const float*)d_in[7];
    // d_in[8] = ba: cancels inside softmax, never read.

    float* att = (float*)d_out;                       // (B, L, D)
    float* enc = att + (size_t)BB * LL * DD;          // (B, L, H)

    float *gx;
    __half* hbuf;
    void* ctr;
    cudaGetSymbolAddress((void**)&gx,   g_Gx);
    cudaGetSymbolAddress((void**)&hbuf, g_h);
    cudaGetSymbolAddress(&ctr,          g_ctr);

    static int smem_set = 0;
    if (!smem_set) {
        cudaFuncSetAttribute(rec_persistent,
                             cudaFuncAttributeMaxDynamicSharedMemorySize, SMEM_REC);
        smem_set = 1;
    }

    // 0) zero per-step barrier counters (captured memset node)
    cudaMemsetAsync(ctr, 0, sizeof(unsigned) * NGRP * LL);

    // 1) attention weights a + att output (fused, round-11 version)
    attn_kernel<<<BB, DD>>>(x, Wa, att);

    // 2) input projection, fp16 m16n8k16 pipeline (a-scaling fused)
    {
        dim3 grid(G4 / 128, (BB * LL) / 128);         // (16, 128)
        gemm_xproj_f16<<<grid, 256>>>(x, Wih, bih, bhh, gx);
    }

    // 3) whole recurrence in ONE persistent fp16 kernel
    rec_persistent<<<NBLK, 256, SMEM_REC>>>(h0, c0, Whh, gx, enc, hbuf);
}

// round 16
// speedup vs baseline: 1.5850x; 1.0034x over previous
#include <cuda_runtime.h>
#include <cuda_fp16.h>
#include <math.h>
#include <stdint.h>

// Problem dims (fixed)
#define BB   256      // batch
#define LL   64       // seq len
#define DD   256      // input dim
#define HH   512      // hidden
#define G4   2048     // 4*H

#define NBLK 128      // persistent grid: 8 batch groups x 16 unit slices
#define NGRP 8        // barrier domains (16 blocks each)
#define MB   32       // batch rows per block
#define UB   32       // units per block (x4 gates = 128 gate-cols)

// -------- scratch (device globals: allocation-free) --------
__device__ float  g_a[BB * DD];                   // attention weights a[b,d]
__device__ float  g_Gx[(size_t)BB * LL * G4];     // 128 MB
__device__ __half g_h[2 * BB * HH];               // ping-pong h (fp16)
__device__ unsigned g_ctr[NGRP][LL];              // per-group per-step arrival counters

// ---------- helpers ----------
__device__ __forceinline__ void mma16(float* c,
                                      uint32_t a0, uint32_t a1, uint32_t a2, uint32_t a3,
                                      uint32_t b0, uint32_t b1)
{
    asm volatile("mma.sync.aligned.m16n8k16.row.col.f32.f16.f16.f32 "
                 "{%0,%1,%2,%3},{%4,%5,%6,%7},{%8,%9},{%0,%1,%2,%3};"
                 : "+f"(c[0]), "+f"(c[1]), "+f"(c[2]), "+f"(c[3])
                 : "r"(a0), "r"(a1), "r"(a2), "r"(a3), "r"(b0), "r"(b1));
}

__device__ __forceinline__ void cpa16(void* dst, const void* src) {
    uint32_t d = (uint32_t)__cvta_generic_to_shared(dst);
    asm volatile("cp.async.cg.shared.global [%0], [%1], 16;" :: "r"(d), "l"(src));
}
#define CPA_COMMIT() asm volatile("cp.async.commit_group;")
#define CPA_WAIT0()  asm volatile("cp.async.wait_group 0;")
#define CPA_WAIT1()  asm volatile("cp.async.wait_group 1;")

__device__ __forceinline__ void bar_arrive(unsigned* p) {
    asm volatile("red.release.gpu.global.add.u32 [%0], 1;" :: "l"(p) : "memory");
}
__device__ __forceinline__ unsigned ld_acq(const unsigned* p) {
    unsigned v;
    asm volatile("ld.acquire.gpu.global.u32 %0, [%1];" : "=r"(v) : "l"(p) : "memory");
    return v;
}

__device__ __forceinline__ float sigf(float x) {
    return __fdividef(1.f, 1.f + __expf(-x));
}
__device__ __forceinline__ float tanhfast(float x) {
    return __fmaf_rn(2.f, __fdividef(1.f, 1.f + __expf(-2.f * x)), -1.f);
}

// ============================================================
// Kernel 1: a = softmax_d(x^T @ Wx); att = a (all t); store a[b,d]
// (recurrent logit term is constant over softmax axis -> cancels)
// ============================================================
__global__ void attn_kernel(const float* __restrict__ x,
                            const float* __restrict__ Wa,
                            float* __restrict__ att)
{
    __shared__ float wx[LL];
    __shared__ float red[DD];
    const int b = blockIdx.x;
    const int d = threadIdx.x;

    if (d < LL) wx[d] = Wa[2 * HH + d];
    __syncthreads();

    const float* xb = x + (size_t)b * LL * DD;
    float ex = 0.f;
#pragma unroll
    for (int l = 0; l < LL; ++l)
        ex += xb[l * DD + d] * wx[l];

    red[d] = ex; __syncthreads();
    for (int s = DD / 2; s > 0; s >>= 1) {
        if (d < s) red[d] = fmaxf(red[d], red[d + s]);
        __syncthreads();
    }
    const float mx = red[0];
    __syncthreads();

    const float e = expf(ex - mx);
    red[d] = e; __syncthreads();
    for (int s = DD / 2; s > 0; s >>= 1) {
        if (d < s) red[d] += red[d + s];
        __syncthreads();
    }
    const float a = e / red[0];

    g_a[b * DD + d] = a;

    __syncthreads();                 // red[0] consumed by all before reuse
    red[d] = a;                      // broadcast a for vectorized stores
    __syncthreads();

    float* attb = att + (size_t)b * LL * DD;
    const int d4 = (d & 63) * 4;
    const float4 av = *(const float4*)&red[d4];
#pragma unroll
    for (int tt = d >> 6; tt < LL; tt += 4)
        *(float4*)&attb[tt * DD + d4] = av;
}

// ============================================================
// Kernel 2: Gx = (a .* x) @ Wih^T + b_ih + b_hh  (16384x2048x256)
// fp16 m16n8k16, f32 accumulate. BM=128 BN=128 BK=32, register-
// prefetch pipeline. Warps: 2(m) x 4(n), warp tile 64x32.
// (At the legacy-mma dispatch floor: ~115us.)
// ============================================================
__global__ __launch_bounds__(256) void gemm_xproj_f16(
    const float* __restrict__ X,
    const float* __restrict__ Bw,
    const float* __restrict__ b1,
    const float* __restrict__ b2,
    float* __restrict__ C)
{
    __shared__ __half As[128 * 40];   // [row][k] halves, stride 40 (conflict-free)
    __shared__ __half Bs[128 * 40];

    const int tid  = threadIdx.x;
    const int lane = tid & 31, warp = tid >> 5;
    const int qid  = lane >> 2, tig = lane & 3;
    const int wm   = warp >> 2;       // 0..1 : 64-row group
    const int wn   = warp & 3;        // 0..3 : 32-col group
    const int m0   = blockIdx.y * 128;
    const int n0   = blockIdx.x * 128;

    const int lr = tid >> 3;          // 0..31
    const int lk = (tid & 7) * 4;     // 0..28

    const float* aptr = X  + (size_t)(m0 + lr) * DD + lk;
    const float* bptr = Bw + (size_t)(n0 + lr) * DD + lk;
    int brow[4];
#pragma unroll
    for (int i = 0; i < 4; ++i) brow[i] = (m0 + lr + i * 32) >> 6;

    float4 pa[4], sa[4], pb[4];
#pragma unroll
    for (int i = 0; i < 4; ++i) {
        pa[i] = *(const float4*)(aptr + (size_t)i * 32 * DD);
        sa[i] = *(const float4*)(g_a + brow[i] * DD + lk);
        pb[i] = *(const float4*)(bptr + (size_t)i * 32 * DD);
    }

    float acc[4][4][4] = {};

    for (int k0 = 0; k0 < DD; k0 += 32) {
#pragma unroll
        for (int i = 0; i < 4; ++i) {
            __half* d = &As[(lr + i * 32) * 40 + lk];
            __half2 h0 = __floats2half2_rn(pa[i].x * sa[i].x, pa[i].y * sa[i].y);
            __half2 h1 = __floats2half2_rn(pa[i].z * sa[i].z, pa[i].w * sa[i].w);
            *(__half2*)(d)     = h0;
            *(__half2*)(d + 2) = h1;
            __half* e = &Bs[(lr + i * 32) * 40 + lk];
            __half2 g0 = __floats2half2_rn(pb[i].x, pb[i].y);
            __half2 g1 = __floats2half2_rn(pb[i].z, pb[i].w);
            *(__half2*)(e)     = g0;
            *(__half2*)(e + 2) = g1;
        }
        __syncthreads();

        if (k0 + 32 < DD) {
#pragma unroll
            for (int i = 0; i < 4; ++i) {
                pa[i] = *(const float4*)(aptr + k0 + 32 + (size_t)i * 32 * DD);
                sa[i] = *(const float4*)(g_a + brow[i] * DD + k0 + 32 + lk);
                pb[i] = *(const float4*)(bptr + k0 + 32 + (size_t)i * 32 * DD);
            }
        }

#pragma unroll
        for (int kk = 0; kk < 2; ++kk) {        // two k16 steps per 32-chunk
            uint32_t af[4][4], bf[4][2];
#pragma unroll
            for (int mt = 0; mt < 4; ++mt) {
                const __half* s = &As[(wm * 64 + mt * 16 + qid) * 40 + kk * 16 + tig * 2];
                af[mt][0] = *(const uint32_t*)(s);
                af[mt][1] = *(const uint32_t*)(s + 8 * 40);
                af[mt][2] = *(const uint32_t*)(s + 8);
                af[mt][3] = *(const uint32_t*)(s + 8 * 40 + 8);
            }
#pragma unroll
            for (int nt = 0; nt < 4; ++nt) {
                const __half* s = &Bs[(wn * 32 + nt * 8 + qid) * 40 + kk * 16 + tig * 2];
                bf[nt][0] = *(const uint32_t*)(s);
                bf[nt][1] = *(const uint32_t*)(s + 8);
            }
#pragma unroll
            for (int mt = 0; mt < 4; ++mt)
#pragma unroll
                for (int nt = 0; nt < 4; ++nt)
                    mma16(acc[mt][nt], af[mt][0], af[mt][1], af[mt][2], af[mt][3],
                          bf[nt][0], bf[nt][1]);
        }
        __syncthreads();
    }

#pragma unroll
    for (int mt = 0; mt < 4; ++mt) {
        const int m = m0 + wm * 64 + mt * 16 + qid;
#pragma unroll
        for (int nt = 0; nt < 4; ++nt) {
            const int n = n0 + wn * 32 + nt * 8 + 2 * tig;
            const float bb0 = b1[n] + b2[n];
            const float bb1 = b1[n + 1] + b2[n + 1];
            float2 o0 = {acc[mt][nt][0] + bb0, acc[mt][nt][1] + bb1};
            float2 o1 = {acc[mt][nt][2] + bb0, acc[mt][nt][3] + bb1};
            *(float2*)(C + (size_t)m * G4 + n)       = o0;
            *(float2*)(C + (size_t)(m + 8) * G4 + n) = o1;
        }
    }
}

// ============================================================
// Kernel 3: PERSISTENT fp16 recurrence.
// 128 blocks = 8 batch groups x 16 unit slices; block tile
// 32 batch x 128 gate-cols, K=512. Whh resident in smem (fp16).
// NEW vs r15: (a) split h-tile wait — MMA on chunks {0,1} starts
// after wait_group(1), chunks {2,3} after wait_group(0);
// (b) enc store moved AFTER the peer arrive (off critical path).
// ============================================================
#define WHH_H  (128 * 520)                // Whh slice, fp16 halves
#define HCH_H  (32 * 72)                  // one 64-K h chunk, fp16 halves
#define GX_F   (32 * 132)                 // Gx tile, f32
#define GT_F   (2 * 32 * 132)             // 2-plane partial-sum exchange, f32
#define SMEM_REC (WHH_H * 2 + 8 * HCH_H * 2 + GX_F * 4 + GT_F * 4)  // 220672 B

__global__ void __launch_bounds__(256, 1) rec_persistent(
    const float* __restrict__ h0,
    const float* __restrict__ c0,
    const float* __restrict__ Whh,
    const float* __restrict__ Gx,
    float* __restrict__ enc,
    __half* __restrict__ hbuf)
{
    extern __shared__ __align__(16) __half smh[];
    __half* WhhS = smh;                         // [128][520]
    __half* hS   = smh + WHH_H;                 // [8][32][72]
    float*  GxS  = (float*)(smh + WHH_H + 8 * HCH_H);  // [32][132]
    float*  Gt   = GxS + GX_F;                  // [2][32][132]

    const int tid  = threadIdx.x;
    const int lane = tid & 31, warp = tid >> 5;
    const int qid  = lane >> 2, tig = lane & 3;
    const int set  = warp >> 2;                 // K half: 0 -> chunks 0-3, 1 -> 4-7
    const int gate = warp & 3;                  // 32-col group
    const int bid  = blockIdx.x;
    const int grp  = bid >> 4;                  // batch group 0..7
    const int m0   = grp * MB;
    const int u0   = (bid & 15) * UB;

    // ---- Whh slice -> smem fp16 (once) ----
    for (int idx = tid; idx < 128 * 128; idx += 256) {
        const int r = idx >> 7, kq = (idx & 127) * 4;
        const float4 v = *(const float4*)&Whh[(size_t)((r >> 5) * HH + u0 + (r & 31)) * HH + kq];
        *(__half2*)&WhhS[r * 520 + kq]     = __floats2half2_rn(v.x, v.y);
        *(__half2*)&WhhS[r * 520 + kq + 2] = __floats2half2_rn(v.z, v.w);
    }

    // ---- h(0) slice -> fp16 ping buffer 0 ----
    for (int idx = tid; idx < MB * UB; idx += 256) {
        const int b = idx >> 5, uu = idx & 31;
        hbuf[(size_t)(m0 + b) * HH + u0 + uu] =
            __float2half_rn(h0[(size_t)(m0 + b) * HH + u0 + uu]);
    }

    // ---- c slice in registers ----
    const int cb = tid >> 3;                    // 0..31 (batch rel)
    const int cu = (tid & 7) * 4;               // unit rel, step 4
    float creg[4];
    {
        const float4 cv = *(const float4*)&c0[(size_t)(m0 + cb) * HH + u0 + cu];
        creg[0] = cv.x; creg[1] = cv.y; creg[2] = cv.z; creg[3] = cv.w;
    }

    __syncthreads();                            // h(0)+Whh writes done block-wide
    if (tid == 0) bar_arrive(&g_ctr[grp][0]);   // publish h(0)

    // per-set h-load indices: 128 threads cover 4 chunks x 4KB
    const int stid = tid & 127;
    const int hr = stid >> 2;                   // row 0..31
    const int hq = (stid & 3) * 8;              // halves 0,8,16,24 (+32 second load)

    for (int t = 0; t < LL; ++t) {
        const __half* hsrc = hbuf + (size_t)(t & 1) * BB * HH;
        __half*       hdst = hbuf + (size_t)((t + 1) & 1) * BB * HH;

        // Gx prefetch for this step (static input; overlaps barrier wait)
        {
            const float* gbase = Gx + ((size_t)m0 * LL + t) * G4 + u0;
#pragma unroll
            for (int i = 0; i < 4; ++i) {
                const int idx = tid + i * 256;
                const int b = idx >> 5, g = (idx >> 3) & 3, q = (idx & 7) * 4;
                cpa16(&GxS[b * 132 + g * 32 + q],
                      gbase + (size_t)b * LL * G4 + g * HH + q);
            }
            CPA_COMMIT();                       // group G
        }

        // ---- per-WARP barrier poll: h(t) ready from the 16 peer blocks ----
        if (lane == 0) {
            const unsigned* ctr = &g_ctr[grp][t];
            while (ld_acq(ctr) < 16u) {}
        }
        __syncwarp();

        // ---- split h-tile load: group A = chunks {0,1}, B = {2,3} ----
#pragma unroll
        for (int j = 0; j < 2; ++j) {
            const int p = set * 4 + j;
            const __half* src = hsrc + (size_t)(m0 + hr) * HH + p * 64;
            cpa16(&hS[p * HCH_H + hr * 72 + hq],      src + hq);
            cpa16(&hS[p * HCH_H + hr * 72 + hq + 32], src + hq + 32);
        }
        CPA_COMMIT();                           // group A
#pragma unroll
        for (int j = 2; j < 4; ++j) {
            const int p = set * 4 + j;
            const __half* src = hsrc + (size_t)(m0 + hr) * HH + p * 64;
            cpa16(&hS[p * HCH_H + hr * 72 + hq],      src + hq);
            cpa16(&hS[p * HCH_H + hr * 72 + hq + 32], src + hq + 32);
        }
        CPA_COMMIT();                           // group B

        float acc[2][4][4] = {};

        // ---- first half: wait G+A, mma chunks {0,1} ----
        CPA_WAIT1();
        asm volatile("bar.sync %0, %1;" :: "r"(1 + set), "r"(128) : "memory");
#pragma unroll
        for (int half = 0; half < 2; ++half) {
            if (half == 1) {                    // second half: wait B
                CPA_WAIT0();
                asm volatile("bar.sync %0, %1;" :: "r"(1 + set), "r"(128) : "memory");
            }
#pragma unroll
            for (int j = 0; j < 2; ++j) {
                const int kc = set * 4 + half * 2 + j;
                const __half* hA = hS + kc * HCH_H;
                const __half* wB = WhhS + kc * 64;
#pragma unroll
                for (int kk = 0; kk < 4; ++kk) {
                    uint32_t af[2][4], bf[4][2];
#pragma unroll
                    for (int mt = 0; mt < 2; ++mt) {
                        const __half* s = hA + (mt * 16 + qid) * 72 + kk * 16 + tig * 2;
                        af[mt][0] = *(const uint32_t*)(s);
                        af[mt][1] = *(const uint32_t*)(s + 8 * 72);
                        af[mt][2] = *(const uint32_t*)(s + 8);
                        af[mt][3] = *(const uint32_t*)(s + 8 * 72 + 8);
                    }
#pragma unroll
                    for (int nt = 0; nt < 4; ++nt) {
                        const __half* s = wB + (gate * 32 + nt * 8 + qid) * 520 + kk * 16 + tig * 2;
                        bf[nt][0] = *(const uint32_t*)(s);
                        bf[nt][1] = *(const uint32_t*)(s + 8);
                    }
#pragma unroll
                    for (int mt = 0; mt < 2; ++mt)
#pragma unroll
                        for (int nt = 0; nt < 4; ++nt)
                            mma16(acc[mt][nt], af[mt][0], af[mt][1], af[mt][2], af[mt][3],
                                  bf[nt][0], bf[nt][1]);
                }
            }
        }

        // ---- epilogue: partials -> 2-plane Gt (disjoint per set) ----
        {
            float* Gp = Gt + set * (32 * 132);
#pragma unroll
            for (int mt = 0; mt < 2; ++mt) {
                const int rl = mt * 16 + qid;
#pragma unroll
                for (int nt = 0; nt < 4; ++nt) {
                    const int cl = gate * 32 + nt * 8 + tig * 2;
                    *(float2*)&Gp[rl * 132 + cl]       = make_float2(acc[mt][nt][0], acc[mt][nt][1]);
                    *(float2*)&Gp[(rl + 8) * 132 + cl] = make_float2(acc[mt][nt][2], acc[mt][nt][3]);
                }
            }
        }
        __syncthreads();                        // block sync #1: Gt complete

        // ---- LSTM cell: sum partials + Gx; store hdst FIRST ----
        float4 ho;
        {
            float gv[4][4];
#pragma unroll
            for (int g = 0; g < 4; ++g) {
                const int off = cb * 132 + g * 32 + cu;
                const float4 p0 = *(const float4*)&Gt[off];
                const float4 p1 = *(const float4*)&Gt[32 * 132 + off];
                const float4 px = *(const float4*)&GxS[off];
                gv[g][0] = p0.x + p1.x + px.x;
                gv[g][1] = p0.y + p1.y + px.y;
                gv[g][2] = p0.z + p1.z + px.z;
                gv[g][3] = p0.w + p1.w + px.w;
            }

            float* hop = &ho.x;
            __half hr4[4];
#pragma unroll
            for (int k = 0; k < 4; ++k) {
                const float si = sigf(gv[0][k]);
                const float sf = sigf(gv[1][k]);
                const float so = sigf(gv[3][k]);
                const float cn = sf * creg[k] + si * tanhfast(gv[2][k]);
                const float hn = so * tanhfast(cn);
                creg[k] = cn;
                hop[k] = hn;
                hr4[k] = __float2half_rn(hn);
            }
            *(uint2*)(hdst + (size_t)(m0 + cb) * HH + u0 + cu) = *(const uint2*)hr4;
        }
        __syncthreads();                        // block sync #2: hdst/Gt/GxS done
        if (tid == 0 && t + 1 < LL) bar_arrive(&g_ctr[grp][t + 1]);

        // ---- enc store AFTER arrive (off the inter-group critical path) ----
        *(float4*)(enc + (size_t)(m0 + cb) * LL * HH + (size_t)t * HH + u0 + cu) = ho;
    }
}

// ============================================================
// Launch
// ============================================================
extern "C" void kernel_launch(void* const* d_in, const int* in_sizes, int n_in,
                              void* d_out, int out_size)
{
    (void)in_sizes; (void)n_in; (void)out_size;
    const float* x   = (const float*)d_in[0];
    const float* h0  = (const float*)d_in[1];
    const float* c0  = (const float*)d_in[2];
    const float* Wih = (const float*)d_in[3];
    const float* Whh = (const float*)d_in[4];
    const float* bih = (const float*)d_in[5];
    const float* bhh = (const float*)d_in[6];
    const float* Wa  = (const float*)d_in[7];
    // d_in[8] = ba: cancels inside softmax, never read.

    float* att = (float*)d_out;                       // (B, L, D)
    float* enc = att + (size_t)BB * LL * DD;          // (B, L, H)

    float *gx;
    __half* hbuf;
    void* ctr;
    cudaGetSymbolAddress((void**)&gx,   g_Gx);
    cudaGetSymbolAddress((void**)&hbuf, g_h);
    cudaGetSymbolAddress(&ctr,          g_ctr);

    static int smem_set = 0;
    if (!smem_set) {
        cudaFuncSetAttribute(rec_persistent,
                             cudaFuncAttributeMaxDynamicSharedMemorySize, SMEM_REC);
        smem_set = 1;
    }

    // 0) zero per-step barrier counters (captured memset node)
    cudaMemsetAsync(ctr, 0, sizeof(unsigned) * NGRP * LL);

    // 1) attention weights a + att output
    attn_kernel<<<BB, DD>>>(x, Wa, att);

    // 2) input projection, fp16 m16n8k16 pipeline (a-scaling fused)
    {
        dim3 grid(G4 / 128, (BB * LL) / 128);         // (16, 128)
        gemm_xproj_f16<<<grid, 256>>>(x, Wih, bih, bhh, gx);
    }

    // 3) whole recurrence in ONE persistent fp16 kernel
    rec_persistent<<<NBLK, 256, SMEM_REC>>>(h0, c0, Whh, gx, enc, hbuf);
}